// round 10
// baseline (speedup 1.0000x reference)
#include <cuda_runtime.h>

// DistanceTransformMap: exact EDT + approx-sqrt (rel err ~2^-23 << 1e-3).
// A) ballot-compress zero-pixel bitmap, stored TRANSPOSED [b][word+1][y]
//    with zero-padded word columns 0 and 13.
// B) per-(batch, 4-column strip) block: load ONLY the 3 needed word-slabs
//    (contiguous, coalesced, 3 LDG/thread), row distances via 64-bit funnel
//    bit-scans, then the proven column expanding search.
//
// Exactness of the EDT (before sqrt):
//  - funnel covers >=33 bits each direction; empty window -> exact global
//    word loop; zero word-pads make boundaries exact; no zero in row ->
//    d >= 384 -> LARGE (matches reference: min attained at j=i is LARGE).
//  - column near window d<=4 unconditional: extra candidates = upper bounds.
//  - far case (best>25): clamped indices land on LARGE pads (left 0..7,
//    right 392..399); LARGE + d^2 > LARGE >= best0 never wins.
// All EDT intermediates are exact integers < 2^24 in fp32.

constexpr int Bn = 4;
constexpr int Hn = 384;
constexpr int Wn = 384;
constexpr int N  = 384;
constexpr int JW = 14;                        // 12 words + 2 zero pads
constexpr float LARGE = 2.0f * (float)(Hn * Hn + Wn * Wn);  // 589824 > 383^2

constexpr int PAD = 8;
constexpr int LWD = N + 2 * PAD;              // 400
constexpr int LWP = 403;                      // padded line stride
constexpr int CPB = 4;                        // columns per block
constexpr int NT  = 384;

__device__ unsigned g_bm_t[Bn * JW * Hn];     // transposed bitmap

// ---------------- Kernel A: ballot compress (transposed store) ----------------
__global__ __launch_bounds__(384) void edt_compress(const float* __restrict__ mask) {
    const int w = threadIdx.x >> 5, lane = threadIdx.x & 31;
    const int L = blockIdx.x * 12 + w;        // global row (blocks never straddle batches)
    const int b = L / Hn, y = L - b * Hn;
    const size_t base = (size_t)L * N;
    unsigned* __restrict__ dstb = g_bm_t + (size_t)b * JW * Hn;
#pragma unroll
    for (int k = 0; k < 12; ++k) {
        const float v = mask[base + lane + 32 * k];
        const unsigned m = __ballot_sync(0xffffffffu, v <= 0.5f);
        if (lane == k) dstb[(k + 1) * Hn + y] = m;   // scatter store, latency-free
    }
    if (lane == 12) dstb[y] = 0u;                    // word pad j=-1
    if (lane == 13) dstb[13 * Hn + y] = 0u;          // word pad j=12
}

// ---------------- Kernel B ----------------
__device__ __forceinline__ float sqrt_approx(float x) {
    float r;
    asm("sqrt.approx.f32 %0, %1;" : "=f"(r) : "f"(x));  // 1 MUFU op, handles 0
    return r;
}

__device__ __forceinline__ float near_far(const float* __restrict__ row,
                                          float best, int i) {
    if (best > 25.0f) {                        // rare exact continuation
        float df = 5.0f;
        int d = 5;
        const int ip = i + PAD;
        while (df * df < best && d < N) {
#pragma unroll
            for (int u = 0; u < 4; ++u) {
                const int jr = min(ip + d + u, LWD - 1);
                const int jl = max(ip - d - u, 0);
                const float e = df + (float)u;
                best = fminf(best, fmaf(e, e, fminf(row[jr], row[jl])));
            }
            df += 4.0f;
            d += 4;
        }
    }
    return best;
}

__global__ __launch_bounds__(NT, 3) void edt_main(float* __restrict__ out) {
    __shared__ unsigned sh_t[3 * Hn];          // 3 word-slabs [q][y]
    __shared__ float lines[CPB * LWP];
    __shared__ float sh_o[Hn * 5];             // output stage [y][c]

    const int t = threadIdx.x;
    const int b = blockIdx.x / (Wn / CPB);
    const int x0 = (blockIdx.x - b * (Wn / CPB)) * CPB;
    const int jw = x0 >> 5;                    // bp0 = x0&31 <= 28

    // 1. Load word-slabs jw-1..jw+1 (one contiguous 4.6KB run) + LARGE pads.
    const unsigned* __restrict__ src = g_bm_t + ((size_t)b * JW + jw) * Hn;
#pragma unroll
    for (int r = 0; r < 3; ++r)
        sh_t[t + NT * r] = src[t + NT * r];
    if (t < CPB * PAD) {
        const int c = t >> 3, o = t & 7;
        lines[c * LWP + o] = LARGE;
        lines[c * LWP + LWD - PAD + o] = LARGE;
    }
    __syncthreads();

    // 2. Row distances: thread owns y=t, computes CPB columns via funnels.
    {
        const int y = t;
        const unsigned wm1 = sh_t[y];
        const unsigned w0  = sh_t[Hn + y];
        const unsigned wp1 = sh_t[2 * Hn + y];
        const unsigned long long vr = ((unsigned long long)wp1 << 32) | w0;
        const unsigned long long vl = ((unsigned long long)w0 << 32) | wm1;
        const int bp0 = x0 & 31;
        const unsigned* __restrict__ gfb = g_bm_t + (size_t)b * JW * Hn;
#pragma unroll
        for (int xl = 0; xl < CPB; ++xl) {
            const int bp = bp0 + xl;           // <= 31
            const int xg = x0 + xl;
            int dr, dl;
            const unsigned long long r64 = vr >> bp;
            if (r64) {
                dr = __ffsll(r64) - 1;
            } else {                            // rare exact fallback (global)
                dr = 0x7fff;
                for (int j = jw + 2; j < 12; ++j) {
                    const unsigned uu = gfb[(j + 1) * Hn + y];
                    if (uu) { dr = j * 32 - xg + __ffs(uu) - 1; break; }
                }
            }
            const unsigned long long l64 = vl << (31 - bp);
            if (l64) {
                dl = __clzll(l64);
            } else {
                dl = 0x7fff;
                for (int j = jw - 2; j >= 0; --j) {
                    const unsigned uu = gfb[(j + 1) * Hn + y];
                    if (uu) { dl = xg - j * 32 - 31 + __clz(uu); break; }
                }
            }
            const int d = min(dl, dr);
            lines[xl * LWP + PAD + y] = (d < 384) ? (float)(d * d) : LARGE;
        }
    }
    __syncthreads();

    // 3. Column search: 12 warps = 3 segments x 4 columns, 4 searches/thread.
    const int w = t >> 5, lane = t & 31;
    const int cl = w & 3, seg = w >> 2;
    const float* __restrict__ row = &lines[cl * LWP];
    const int ibase = seg * 128 + lane;

    float best[4];
#pragma unroll
    for (int gq = 0; gq < 4; gq += 2) {
        float a[2][9];
#pragma unroll
        for (int s = 0; s < 2; ++s) {
            const float* p = row + PAD + ibase + 32 * (gq + s);
            a[s][0] = p[0];
            a[s][1] = p[1];  a[s][2] = p[-1];
            a[s][3] = p[2];  a[s][4] = p[-2];
            a[s][5] = p[3];  a[s][6] = p[-3];
            a[s][7] = p[4];  a[s][8] = p[-4];
        }
#pragma unroll
        for (int s = 0; s < 2; ++s) {
            const float c1 = fminf(a[s][1], a[s][2]) + 1.0f;
            const float c2 = fminf(a[s][3], a[s][4]) + 4.0f;
            const float c3 = fminf(a[s][5], a[s][6]) + 9.0f;
            const float c4 = fminf(a[s][7], a[s][8]) + 16.0f;
            best[gq + s] = fminf(a[s][0], fminf(fminf(c1, c2), fminf(c3, c4)));
        }
    }
#pragma unroll
    for (int s = 0; s < 4; ++s)
        best[s] = near_far(row, best[s], ibase + 32 * s);

#pragma unroll
    for (int s = 0; s < 4; ++s)
        sh_o[(ibase + 32 * s) * 5 + cl] = sqrt_approx(best[s]);
    __syncthreads();

    // 4. Tile store: 4 floats per y, 8 sectors per warp-store.
    const int c_st = t & 3, y_st = t >> 2;
    float* __restrict__ dst = out + ((size_t)b * Hn) * Wn + x0 + c_st;
#pragma unroll
    for (int r = 0; r < 4; ++r) {
        const int y = y_st + 96 * r;
        dst[(size_t)y * Wn] = sh_o[y * 5 + c_st];
    }
}

extern "C" void kernel_launch(void* const* d_in, const int* in_sizes, int n_in,
                              void* d_out, int out_size) {
    const float* mask = (const float*)d_in[0];
    float* out = (float*)d_out;
    (void)in_sizes; (void)n_in; (void)out_size;

    edt_compress<<<Bn * Hn / 12, 384>>>(mask);
    edt_main<<<Bn * (Wn / CPB), NT>>>(out);
}